// round 15
// baseline (speedup 1.0000x reference)
#include <cuda_runtime.h>

// SigMMDLoss: B=4096 rows, T=4096, two input tensors (real, gen), scalar f32 out.
//
// Per-row (N = T-1 = 4095 increments dx_k = p[k+1]-p[k]):
//   f1 = sum dx            = p[N] - p[0]                        (telescoped)
//   f3 = dt*sum (k+1)dx    = p[N] - (sum_{j<N} p[j]) / N        (Abel summation)
//   f4 = sum cum(dx)*dx    = 0.5 * (f1^2 + sum dx^2)            (closed form)
//   f6 = sum dx^2
//   f8 = sum dx^3
// Time-only features cancel exactly between real/gen -> skipped.
// loss = sum_i (mean_real f_i - mean_gen f_i)^2
//
// Kernel 1 (producer): BYTE-PURE streaming (R11/R13 body) + one
// griddepcontrol trigger at block START so the dependent kernel dispatches
// when the last wave BEGINS (not ends). No smem/atomics/fences.
// Kernel 2 (consumer, PDL): polls per-row sentinel partials (q>0 always;
// 16B STG = one L2 transaction -> data+doneness together, no ordering ops),
// then the proven int64 fixed-point reduction + acq_rel counter + winner.
// Under ncu kernel serialization the polls hit immediately (no deadlock).

#define T_LEN    4096
#define NROWS    4096
#define NBLOCKS  (2 * NROWS)
#define RT       128                  // threads per block (4 warps)
#define WELEMS   1024                 // contiguous floats owned per warp
#define NFEAT    5
#define FP_SCALE 268435456.0          // 2^28 fixed-point scale
#define R2T      128                  // consumer threads
#define R2B      (NBLOCKS / R2T)      // 64 consumer blocks

__device__ float4 g_wp[NBLOCKS * 4];          // per-warp partials {q,c,sp,edge}
__device__ unsigned long long g_acc[NFEAT];   // fixed-point totals
__device__ unsigned int g_ctr = 0;            // self-resets each launch

// ---- packed f32x2 helpers (Blackwell; only reachable via PTX) ----
__device__ __forceinline__ unsigned long long pk2(float lo, float hi) {
    unsigned long long r;
    asm("mov.b64 %0, {%1, %2};" : "=l"(r) : "f"(lo), "f"(hi));
    return r;
}
__device__ __forceinline__ void upk2(unsigned long long p, float& lo, float& hi) {
    asm("mov.b64 {%0, %1}, %2;" : "=f"(lo), "=f"(hi) : "l"(p));
}
__device__ __forceinline__ unsigned long long fma2(unsigned long long a,
                                                   unsigned long long b,
                                                   unsigned long long c) {
    unsigned long long d;
    asm("fma.rn.f32x2 %0, %1, %2, %3;" : "=l"(d) : "l"(a), "l"(b), "l"(c));
    return d;
}
__device__ __forceinline__ unsigned long long add2(unsigned long long a,
                                                   unsigned long long b) {
    unsigned long long d;
    asm("add.rn.f32x2 %0, %1, %2;" : "=l"(d) : "l"(a), "l"(b));
    return d;
}
__device__ __forceinline__ unsigned long long mul2(unsigned long long a,
                                                   unsigned long long b) {
    unsigned long long d;
    asm("mul.rn.f32x2 %0, %1, %2;" : "=l"(d) : "l"(a), "l"(b));
    return d;
}
__device__ __forceinline__ void redg_add(unsigned long long* addr,
                                         unsigned long long val) {
    asm volatile("red.relaxed.gpu.global.add.u64 [%0], %1;"
                 :: "l"(addr), "l"(val) : "memory");
}
// L2-coherent vector load (bypasses L1; fresh on every poll).
__device__ __forceinline__ float4 ldcg4(const float4* a) {
    float4 r;
    asm volatile("ld.global.cg.v4.f32 {%0,%1,%2,%3}, [%4];"
                 : "=f"(r.x), "=f"(r.y), "=f"(r.z), "=f"(r.w) : "l"(a));
    return r;
}

__global__ __launch_bounds__(RT) void sigmmd_row_kernel(
    const float* __restrict__ real_paths,
    const float* __restrict__ gen_paths)
{
    // Fire the PDL trigger at block START: once all blocks have begun
    // (i.e., when the last wave starts), the consumer kernel dispatches.
    cudaTriggerProgrammaticLaunchCompletion();

    const int bid = blockIdx.x;
    const float* base = (bid < NROWS) ? real_paths : gen_paths;
    const int row = bid & (NROWS - 1);
    const float* p = base + (size_t)row * T_LEN;
    const int tid  = threadIdx.x;
    const int lane = tid & 31;
    const int w    = tid >> 5;

    // ---- Warp-coalesced float4 streaming (no inter-warp coupling) ----
    const float4* b4 = (const float4*)p + w * (WELEMS / 4);
    float4 v[8];
#pragma unroll
    for (int i = 0; i < 8; i++) v[i] = __ldcs(b4 + i * 32 + lane);

    // Predecessor of this warp's first element (only lane 0 uses it).
    // Warp 0 lane 0: phantom dx = 0 (prev = first element itself).
    float carry = 0.f;
    if (lane == 0) carry = (w == 0) ? v[0].x : __ldcs(p + w * WELEMS - 1);

    const unsigned long long NEG1 = pk2(-1.0f, -1.0f);
    unsigned long long qp = 0ull, cp = 0ull, spp = 0ull;
#pragma unroll
    for (int i = 0; i < 8; i++) {
        float4 c4 = v[i];
        float pl = __shfl_up_sync(0xffffffffu, c4.w, 1);
        float prev = (lane == 0) ? carry : pl;
        unsigned long long cur0 = pk2(c4.x, c4.y);
        unsigned long long cur1 = pk2(c4.z, c4.w);
        unsigned long long prv0 = pk2(prev, c4.x);
        unsigned long long prv1 = pk2(c4.y, c4.z);
        unsigned long long dx0 = fma2(prv0, NEG1, cur0);   // cur - prv
        unsigned long long dx1 = fma2(prv1, NEG1, cur1);
        unsigned long long t0 = mul2(dx0, dx0);
        unsigned long long t1 = mul2(dx1, dx1);
        qp  = add2(qp, add2(t0, t1));                      // sum dx^2
        cp  = fma2(t0, dx0, cp);                           // sum dx^3
        cp  = fma2(t1, dx1, cp);
        spp = add2(spp, add2(cur0, cur1));                 // sum p
        carry = __shfl_sync(0xffffffffu, c4.w, 31);        // warp's running last
    }
    float ql, qh, cl, ch, sl, sh;
    upk2(qp, ql, qh); upk2(cp, cl, ch); upk2(spp, sl, sh);
    float q = ql + qh, c = cl + ch, sp = sl + sh;
    if (tid == RT - 1) sp -= v[7].w;   // sum p covers p[0..N-1] only

    // Warp tree reduce (fp32, deterministic)
#pragma unroll
    for (int off = 16; off; off >>= 1) {
        q  += __shfl_down_sync(0xffffffffu, q,  off);
        c  += __shfl_down_sync(0xffffffffu, c,  off);
        sp += __shfl_down_sync(0xffffffffu, sp, off);
    }
    if (lane == 0) {
        // q > 0 always (sum of squares of nonzero increments) -> q doubles
        // as the doneness sentinel. One STG.128 = one L2 transaction.
        float edge = (w == 0) ? v[0].x : carry;
        g_wp[bid * 4 + w] = make_float4(q, c, sp, edge);
    }
}

// Consumer (PDL secondary): polls sentinels, reduces, writes the loss.
__global__ __launch_bounds__(R2T) void sigmmd_reduce_kernel(float* __restrict__ out)
{
    const int tid = threadIdx.x;
    const int lane = tid & 31;
    const int wid = tid >> 5;
    const int r = blockIdx.x * R2T + tid;     // one row per thread

    float4 a, b, c, d;
    const float4* slot = &g_wp[r * 4];
    a = ldcg4(slot + 0);
    b = ldcg4(slot + 1);
    c = ldcg4(slot + 2);
    d = ldcg4(slot + 3);
    while (a.x == 0.f || b.x == 0.f || c.x == 0.f || d.x == 0.f) {
        __nanosleep(128);
        if (a.x == 0.f) a = ldcg4(slot + 0);
        if (b.x == 0.f) b = ldcg4(slot + 1);
        if (c.x == 0.f) c = ldcg4(slot + 2);
        if (d.x == 0.f) d = ldcg4(slot + 3);
    }
    // Reset slots for the next graph replay (kernel boundary publishes).
    slot_reset: ;
    g_wp[r * 4 + 0] = make_float4(0.f, 0.f, 0.f, 0.f);
    g_wp[r * 4 + 1] = make_float4(0.f, 0.f, 0.f, 0.f);
    g_wp[r * 4 + 2] = make_float4(0.f, 0.f, 0.f, 0.f);
    g_wp[r * 4 + 3] = make_float4(0.f, 0.f, 0.f, 0.f);

    // Same promotion order as before: warp 0,1,2,3.
    double Q  = (((double)a.x + (double)b.x) + (double)c.x) + (double)d.x;
    double C  = (((double)a.y + (double)b.y) + (double)c.y) + (double)d.y;
    double SP = (((double)a.z + (double)b.z) + (double)c.z) + (double)d.z;
    double p0 = (double)a.w;
    double pN = (double)d.w;
    double S1 = pN - p0;
    const double sgn = (r < NROWS) ? FP_SCALE : -FP_SCALE;

    long long fi[NFEAT];
    fi[0] = __double2ll_rn(sgn * S1);
    fi[1] = __double2ll_rn(sgn * (pN - SP / 4095.0));
    fi[2] = __double2ll_rn(sgn * (0.5 * (S1 * S1 + Q)));
    fi[3] = __double2ll_rn(sgn * Q);
    fi[4] = __double2ll_rn(sgn * C);

    // Integer warp tree (associative -> deterministic)
#pragma unroll
    for (int off = 16; off; off >>= 1)
#pragma unroll
        for (int i = 0; i < NFEAT; i++)
            fi[i] += __shfl_down_sync(0xffffffffu, fi[i], off);

    __shared__ long long s_f[R2T / 32][NFEAT];
    if (lane == 0)
#pragma unroll
        for (int i = 0; i < NFEAT; i++) s_f[wid][i] = fi[i];
    __syncthreads();
    if (tid != 0) return;

    unsigned int prevc;
    {
        long long tot[NFEAT];
#pragma unroll
        for (int i = 0; i < NFEAT; i++) {
            tot[i] = ((s_f[0][i] + s_f[1][i]) + s_f[2][i]) + s_f[3][i];
            redg_add(&g_acc[i], (unsigned long long)tot[i]);
        }
        // acq_rel: release orders the REDGs above; acquire lets the winner
        // read fresh totals. Only 64 of these per launch.
        asm volatile("atom.acq_rel.gpu.global.add.u32 %0, [%1], %2;"
                     : "=r"(prevc) : "l"(&g_ctr), "r"(1u) : "memory");
    }
    if (prevc == R2B - 1) {
        double loss = 0.0;
#pragma unroll
        for (int i = 0; i < NFEAT; i++) {
            long long t = __ldcg((const long long*)&g_acc[i]);
            double m = ((double)t / FP_SCALE) / (double)NROWS;
            loss += m * m;
        }
        out[0] = (float)loss;
        // Reset for next graph replay (kernel boundary publishes).
#pragma unroll
        for (int i = 0; i < NFEAT; i++) g_acc[i] = 0ull;
        g_ctr = 0;
    }
}

extern "C" void kernel_launch(void* const* d_in, const int* in_sizes, int n_in,
                              void* d_out, int out_size)
{
    const float* real_paths = (const float*)d_in[0];
    const float* gen_paths  = (const float*)d_in[1];
    float* out = (float*)d_out;

    sigmmd_row_kernel<<<NBLOCKS, RT>>>(real_paths, gen_paths);

    // PDL: consumer dispatches once every producer block has STARTED
    // (trigger at block top), overlapping the producer's drain. It needs no
    // grid sync — it polls per-row sentinels.
    cudaLaunchConfig_t cfg = {};
    cfg.gridDim = dim3(R2B, 1, 1);
    cfg.blockDim = dim3(R2T, 1, 1);
    cfg.dynamicSmemBytes = 0;
    cudaLaunchAttribute attr[1];
    attr[0].id = cudaLaunchAttributeProgrammaticStreamSerialization;
    attr[0].val.programmaticStreamSerializationAllowed = 1;
    cfg.attrs = attr;
    cfg.numAttrs = 1;
    cudaLaunchKernelEx(&cfg, sigmmd_reduce_kernel, out);
}

// round 16
// speedup vs baseline: 1.2884x; 1.2884x over previous
#include <cuda_runtime.h>

// SigMMDLoss: B=4096 rows, T=4096, two input tensors (real, gen), scalar f32 out.
//
// Per-row (N = T-1 = 4095 increments dx_k = p[k+1]-p[k]):
//   f1 = sum dx            = p[N] - p[0]                        (telescoped)
//   f3 = dt*sum (k+1)dx    = p[N] - (sum_{j<N} p[j]) / N        (Abel summation)
//   f4 = sum cum(dx)*dx    = 0.5 * (f1^2 + sum dx^2)            (closed form)
//   f6 = sum dx^2
//   f8 = sum dx^3
// Time-only features cancel exactly between real/gen -> skipped.
// loss = sum_i (mean_real f_i - mean_gen f_i)^2
//
// Kernel 1 (producer): BYTE-PURE streaming. Each warp owns 2048 contiguous
// floats (16 front-batched LDG.128 -> MLP 16); block = 4 warps = 2 rows;
// grid = 4096. lane0 stores one float4 {q,c,sp,edge} per half-row.
// No smem/syncthreads/fp64/atomics.
// Kernel 2 (consumer, PDL grid-sync, R13-proven): one thread per row reads
// 2 partials, fp64 features in fixed order, int64 fixed-point reduction
// (associative -> deterministic), REDG + acq_rel counter, winner writes out.

#define T_LEN    4096
#define NROWS    4096
#define NROWTOT  (2 * NROWS)          // 8192 rows across both tensors
#define RT       128                  // producer threads (4 warps = 2 rows)
#define NPBLK    (NROWTOT / 2)        // 4096 producer blocks
#define WELEMS   2048                 // contiguous floats owned per warp
#define NFEAT    5
#define FP_SCALE 268435456.0          // 2^28 fixed-point scale
#define R2T      128                  // consumer threads
#define R2B      (NROWTOT / R2T)      // 64 consumer blocks

__device__ float4 g_wp[NROWTOT * 2];          // per-half-row {q,c,sp,edge}
__device__ unsigned long long g_acc[NFEAT];   // fixed-point totals
__device__ unsigned int g_ctr = 0;            // self-resets each launch

// ---- packed f32x2 helpers (Blackwell; only reachable via PTX) ----
__device__ __forceinline__ unsigned long long pk2(float lo, float hi) {
    unsigned long long r;
    asm("mov.b64 %0, {%1, %2};" : "=l"(r) : "f"(lo), "f"(hi));
    return r;
}
__device__ __forceinline__ void upk2(unsigned long long p, float& lo, float& hi) {
    asm("mov.b64 {%0, %1}, %2;" : "=f"(lo), "=f"(hi) : "l"(p));
}
__device__ __forceinline__ unsigned long long fma2(unsigned long long a,
                                                   unsigned long long b,
                                                   unsigned long long c) {
    unsigned long long d;
    asm("fma.rn.f32x2 %0, %1, %2, %3;" : "=l"(d) : "l"(a), "l"(b), "l"(c));
    return d;
}
__device__ __forceinline__ unsigned long long add2(unsigned long long a,
                                                   unsigned long long b) {
    unsigned long long d;
    asm("add.rn.f32x2 %0, %1, %2;" : "=l"(d) : "l"(a), "l"(b));
    return d;
}
__device__ __forceinline__ unsigned long long mul2(unsigned long long a,
                                                   unsigned long long b) {
    unsigned long long d;
    asm("mul.rn.f32x2 %0, %1, %2;" : "=l"(d) : "l"(a), "l"(b));
    return d;
}
__device__ __forceinline__ void redg_add(unsigned long long* addr,
                                         unsigned long long val) {
    asm volatile("red.relaxed.gpu.global.add.u64 [%0], %1;"
                 :: "l"(addr), "l"(val) : "memory");
}

__global__ __launch_bounds__(RT) void sigmmd_row_kernel(
    const float* __restrict__ real_paths,
    const float* __restrict__ gen_paths)
{
    const int tid  = threadIdx.x;
    const int lane = tid & 31;
    const int w    = tid >> 5;                 // 0..3
    const int g    = blockIdx.x * 2 + (w >> 1);  // global row id (0..8191)
    const int half = w & 1;                    // which half of the row
    const float* base = (g < NROWS) ? real_paths : gen_paths;
    const int row = g & (NROWS - 1);
    const float* p = base + (size_t)row * T_LEN;

    // ---- Warp-coalesced float4 streaming: 16 front-batched LDG.128 ----
    const float4* b4 = (const float4*)p + half * (WELEMS / 4);
    float4 v[16];
#pragma unroll
    for (int i = 0; i < 16; i++) v[i] = __ldcs(b4 + i * 32 + lane);

    // Predecessor of this warp's first element (only lane 0 uses it).
    // First half: phantom dx = 0 (prev = first element itself).
    float carry = 0.f;
    if (lane == 0) carry = (half == 0) ? v[0].x : __ldcs(p + WELEMS - 1);

    const unsigned long long NEG1 = pk2(-1.0f, -1.0f);
    unsigned long long qp = 0ull, cp = 0ull, spp = 0ull;
#pragma unroll
    for (int i = 0; i < 16; i++) {
        float4 c4 = v[i];
        float pl = __shfl_up_sync(0xffffffffu, c4.w, 1);
        float prev = (lane == 0) ? carry : pl;
        unsigned long long cur0 = pk2(c4.x, c4.y);
        unsigned long long cur1 = pk2(c4.z, c4.w);
        unsigned long long prv0 = pk2(prev, c4.x);
        unsigned long long prv1 = pk2(c4.y, c4.z);
        unsigned long long dx0 = fma2(prv0, NEG1, cur0);   // cur - prv
        unsigned long long dx1 = fma2(prv1, NEG1, cur1);
        unsigned long long t0 = mul2(dx0, dx0);
        unsigned long long t1 = mul2(dx1, dx1);
        qp  = add2(qp, add2(t0, t1));                      // sum dx^2
        cp  = fma2(t0, dx0, cp);                           // sum dx^3
        cp  = fma2(t1, dx1, cp);
        spp = add2(spp, add2(cur0, cur1));                 // sum p
        carry = __shfl_sync(0xffffffffu, c4.w, 31);        // warp's running last
    }
    float ql, qh, cl, ch, sl, sh;
    upk2(qp, ql, qh); upk2(cp, cl, ch); upk2(spp, sl, sh);
    float q = ql + qh, c = cl + ch, sp = sl + sh;
    // sp must cover p[0..N-1] only: second half's lane31 owns p[N] in v[15].w
    if (half == 1 && lane == 31) sp -= v[15].w;

    // Warp tree reduce (fp32, deterministic)
#pragma unroll
    for (int off = 16; off; off >>= 1) {
        q  += __shfl_down_sync(0xffffffffu, q,  off);
        c  += __shfl_down_sync(0xffffffffu, c,  off);
        sp += __shfl_down_sync(0xffffffffu, sp, off);
    }
    if (lane == 0) {
        // edge: half0 -> row's p[0]; half1 -> row's p[N] (carry = last elem)
        float edge = (half == 0) ? v[0].x : carry;
        g_wp[g * 2 + half] = make_float4(q, c, sp, edge);
    }
    // Allow the dependent reduce kernel to be dispatched early.
    cudaTriggerProgrammaticLaunchCompletion();
}

// Kernel 2 (PDL consumer): one thread per row; fp64 feature math in fixed
// order; int64 fixed-point block reduce; REDG + acq_rel counter; winner out.
__global__ __launch_bounds__(R2T) void sigmmd_reduce_kernel(float* __restrict__ out)
{
    const int tid = threadIdx.x;
    const int lane = tid & 31;
    const int wid = tid >> 5;
    const int r = blockIdx.x * R2T + tid;

    // Wait for the producer grid to complete.
    cudaGridDependencySynchronize();

    float4 a = g_wp[r * 2 + 0];
    float4 b = g_wp[r * 2 + 1];

    double Q  = (double)a.x + (double)b.x;
    double C  = (double)a.y + (double)b.y;
    double SP = (double)a.z + (double)b.z;
    double p0 = (double)a.w;
    double pN = (double)b.w;
    double S1 = pN - p0;
    const double sgn = (r < NROWS) ? FP_SCALE : -FP_SCALE;

    long long fi[NFEAT];
    fi[0] = __double2ll_rn(sgn * S1);
    fi[1] = __double2ll_rn(sgn * (pN - SP / 4095.0));
    fi[2] = __double2ll_rn(sgn * (0.5 * (S1 * S1 + Q)));
    fi[3] = __double2ll_rn(sgn * Q);
    fi[4] = __double2ll_rn(sgn * C);

    // Integer warp tree (associative -> deterministic)
#pragma unroll
    for (int off = 16; off; off >>= 1)
#pragma unroll
        for (int i = 0; i < NFEAT; i++)
            fi[i] += __shfl_down_sync(0xffffffffu, fi[i], off);

    __shared__ long long s_f[R2T / 32][NFEAT];
    if (lane == 0)
#pragma unroll
        for (int i = 0; i < NFEAT; i++) s_f[wid][i] = fi[i];
    __syncthreads();
    if (tid != 0) return;

    unsigned int prevc;
    {
        long long tot[NFEAT];
#pragma unroll
        for (int i = 0; i < NFEAT; i++) {
            tot[i] = ((s_f[0][i] + s_f[1][i]) + s_f[2][i]) + s_f[3][i];
            redg_add(&g_acc[i], (unsigned long long)tot[i]);
        }
        // acq_rel: release orders the REDGs above; acquire lets the winner
        // read fresh totals. Only 64 of these per launch.
        asm volatile("atom.acq_rel.gpu.global.add.u32 %0, [%1], %2;"
                     : "=r"(prevc) : "l"(&g_ctr), "r"(1u) : "memory");
    }
    if (prevc == R2B - 1) {
        double loss = 0.0;
#pragma unroll
        for (int i = 0; i < NFEAT; i++) {
            long long t = __ldcg((const long long*)&g_acc[i]);
            double m = ((double)t / FP_SCALE) / (double)NROWS;
            loss += m * m;
        }
        out[0] = (float)loss;
        // Reset for next graph replay (kernel boundary publishes).
#pragma unroll
        for (int i = 0; i < NFEAT; i++) g_acc[i] = 0ull;
        g_ctr = 0;
    }
}

extern "C" void kernel_launch(void* const* d_in, const int* in_sizes, int n_in,
                              void* d_out, int out_size)
{
    const float* real_paths = (const float*)d_in[0];
    const float* gen_paths  = (const float*)d_in[1];
    float* out = (float*)d_out;

    sigmmd_row_kernel<<<NPBLK, RT>>>(real_paths, gen_paths);

    // PDL launch (R13-proven): reduce kernel dispatches before the row
    // kernel retires; cudaGridDependencySynchronize() provides ordering.
    cudaLaunchConfig_t cfg = {};
    cfg.gridDim = dim3(R2B, 1, 1);
    cfg.blockDim = dim3(R2T, 1, 1);
    cfg.dynamicSmemBytes = 0;
    cudaLaunchAttribute attr[1];
    attr[0].id = cudaLaunchAttributeProgrammaticStreamSerialization;
    attr[0].val.programmaticStreamSerializationAllowed = 1;
    cfg.attrs = attr;
    cfg.numAttrs = 1;
    cudaLaunchKernelEx(&cfg, sigmmd_reduce_kernel, out);
}